// round 2
// baseline (speedup 1.0000x reference)
#include <cuda_runtime.h>
#include <cstdint>

#define NN 8192
#define T  1024
#define SCORE_TH 0.5f
#define IOU_TH   0.5f

// Global scratch (no allocations allowed)
__device__ float4 g_boxes_s[NN];
__device__ float  g_conf_s[NN];
__device__ int    g_M;

// ---------------------------------------------------------------------------
// Kernel 1: max-reduce conf, normalize, stable descending sort (bitonic on
// packed 64-bit keys), scatter sorted xyxy boxes + conf, count valid prefix M.
// ---------------------------------------------------------------------------
__global__ void __launch_bounds__(T, 1) sort_kernel(const float* __restrict__ in) {
    extern __shared__ unsigned long long skey[];   // 8192 * 8 = 64 KB dynamic
    __shared__ float sred[32];
    __shared__ int   sicnt[32];
    const int tid = threadIdx.x;

    // --- load raw conf (8 per thread), block max reduce ---
    float c[8];
    float m = 0.0f;                 // conf values are uniform[0,1) -> nonneg
    #pragma unroll
    for (int u = 0; u < 8; u++) {
        int l = tid + u * T;
        c[u] = in[l * 5 + 4];
        m = fmaxf(m, c[u]);
    }
    #pragma unroll
    for (int o = 16; o; o >>= 1) m = fmaxf(m, __shfl_xor_sync(0xFFFFFFFFu, m, o));
    if ((tid & 31) == 0) sred[tid >> 5] = m;
    __syncthreads();
    if (tid < 32) {
        float v = sred[tid];
        #pragma unroll
        for (int o = 16; o; o >>= 1) v = fmaxf(v, __shfl_xor_sync(0xFFFFFFFFu, v, o));
        if (tid == 0) sred[0] = v;
    }
    __syncthreads();
    const float mx = sred[0];

    // --- build composite keys: (~conf_bits) desc-as-asc | idx (stable tie) ---
    #pragma unroll
    for (int u = 0; u < 8; u++) {
        int l = tid + u * T;
        float conf = __fdiv_rn(c[u], mx);             // IEEE div, matches jnp
        unsigned int b = __float_as_uint(conf);       // conf >= 0: bits monotone
        skey[l] = ((unsigned long long)(~b) << 32) | (unsigned int)l;
    }
    __syncthreads();

    // --- bitonic sort ascending (=> conf descending, stable) ---
    for (int k = 2; k <= NN; k <<= 1) {
        for (int j = k >> 1; j > 0; j >>= 1) {
            #pragma unroll
            for (int u = 0; u < 8; u++) {
                int l = tid + u * T;
                int p = l ^ j;
                if (p > l) {
                    unsigned long long a = skey[l];
                    unsigned long long b = skey[p];
                    bool up = ((l & k) == 0);
                    if ((a > b) == up) { skey[l] = b; skey[p] = a; }
                }
            }
            __syncthreads();
        }
    }

    // --- scatter sorted boxes (cxcywh -> xyxy, no FMA contraction) + conf ---
    int cnt = 0;
    #pragma unroll
    for (int u = 0; u < 8; u++) {
        int p = tid + u * T;
        unsigned long long key = skey[p];
        int idx = (int)(key & 0xFFFFFFFFull);
        float conf = __uint_as_float(~(unsigned int)(key >> 32));
        const float* bp = in + idx * 5;
        float cx = bp[0], cy = bp[1], w = bp[2], h = bp[3];
        float hw = __fmul_rn(w, 0.5f);
        float hh = __fmul_rn(h, 0.5f);
        float4 box = make_float4(__fsub_rn(cx, hw), __fsub_rn(cy, hh),
                                 __fadd_rn(cx, hw), __fadd_rn(cy, hh));
        g_boxes_s[p] = box;
        g_conf_s[p]  = conf;
        cnt += (conf >= SCORE_TH) ? 1 : 0;
    }
    #pragma unroll
    for (int o = 16; o; o >>= 1) cnt += __shfl_xor_sync(0xFFFFFFFFu, cnt, o);
    if ((tid & 31) == 0) sicnt[tid >> 5] = cnt;
    __syncthreads();
    if (tid == 0) {
        int s = 0;
        #pragma unroll
        for (int w2 = 0; w2 < 32; w2++) s += sicnt[w2];
        g_M = s;   // valid elements form a prefix of the sorted order
    }
}

// ---------------------------------------------------------------------------
// Kernel 2: greedy NMS over sorted prefix [0, M) entirely in smem, then emit
// all 8192 output rows (zeros where suppressed/invalid).
// Serial loop visits only KEPT rows; 1024 threads suppress candidates with
// exclusive byte ownership (r ≡ tid mod T) -> no atomics needed.
// ---------------------------------------------------------------------------
__global__ void __launch_bounds__(T, 1) nms_kernel(float* __restrict__ out) {
    extern __shared__ unsigned char dyn[];
    float4*        sbox  = (float4*)dyn;                          // 128 KB
    float*         sarea = (float*)(dyn + NN * 16);               //  32 KB
    unsigned char* skeep = (unsigned char*)(dyn + NN * 20);       //   8 KB
    __shared__ int    s_i;
    __shared__ float4 s_box;
    __shared__ float  s_area;

    const int tid = threadIdx.x;
    const int M = g_M;

    for (int p = tid; p < NN; p += T) {
        float4 b = g_boxes_s[p];
        sbox[p]  = b;
        sarea[p] = __fmul_rn(__fsub_rn(b.z, b.x), __fsub_rn(b.w, b.y));
        skeep[p] = (p < M) ? 1 : 0;
    }
    if (tid == 0) s_i = -1;
    __syncthreads();

    while (true) {
        if (tid == 0) {
            int i = s_i + 1;
            while (i < M && !skeep[i]) i++;      // skip suppressed rows (cheap)
            s_i = i;
            if (i < M) { s_box = sbox[i]; s_area = sarea[i]; }
        }
        __syncthreads();
        const int i = s_i;
        if (i >= M) break;
        const float4 bi = s_box;
        const float  ai = s_area;
        for (int r = tid; r < M; r += T) {
            if (r > i && skeep[r]) {
                float4 bj = sbox[r];
                float ix1 = fmaxf(bi.x, bj.x);
                float iy1 = fmaxf(bi.y, bj.y);
                float ix2 = fminf(bi.z, bj.z);
                float iy2 = fminf(bi.w, bj.w);
                float iw  = fmaxf(__fsub_rn(ix2, ix1), 0.0f);
                float ih  = fmaxf(__fsub_rn(iy2, iy1), 0.0f);
                float inter = __fmul_rn(iw, ih);
                float uni   = __fsub_rn(__fadd_rn(ai, sarea[r]), inter);
                float iou   = __fdiv_rn(inter, fmaxf(uni, 1e-9f));
                if (iou > IOU_TH) skeep[r] = 0;
            }
        }
        __syncthreads();
    }

    // --- emit output: [x1 y1 x2 y2 conf] or zeros ---
    for (int p = tid; p < NN; p += T) {
        float4 b = make_float4(0.f, 0.f, 0.f, 0.f);
        float  cf = 0.f;
        if (skeep[p]) { b = sbox[p]; cf = g_conf_s[p]; }
        float* o = out + p * 5;
        o[0] = b.x; o[1] = b.y; o[2] = b.z; o[3] = b.w; o[4] = cf;
    }
}

// ---------------------------------------------------------------------------
extern "C" void kernel_launch(void* const* d_in, const int* in_sizes, int n_in,
                              void* d_out, int out_size) {
    const float* in = (const float*)d_in[0];
    float* out = (float*)d_out;

    cudaFuncSetAttribute(sort_kernel, cudaFuncAttributeMaxDynamicSharedMemorySize,
                         NN * 8);
    cudaFuncSetAttribute(nms_kernel, cudaFuncAttributeMaxDynamicSharedMemorySize,
                         NN * 21);

    sort_kernel<<<1, T, NN * 8>>>(in);
    nms_kernel<<<1, T, NN * 21>>>(out);
}

// round 4
// speedup vs baseline: 1.0242x; 1.0242x over previous
#include <cuda_runtime.h>
#include <cstdint>

#define NN 8192
#define SCORE_TH 0.5f
#define IOU_TH   0.5f

// Global scratch (no allocations allowed)
__device__ float4 g_boxes_s[NN];
__device__ float  g_conf_s[NN];

// ---------------------------------------------------------------------------
// Kernel 1: full-chip stable-rank computation (replaces the sort).
// 128 blocks x 128 threads. Each block owns 64 elements; 2 threads per
// element split the 8192-key scan in half. Each block redundantly builds the
// key table (max-normalize conf, key = ~bits -> ascending = conf descending,
// ties broken by index during counting = stable argsort(-conf)).
// ---------------------------------------------------------------------------
#define RT   128     // threads per block
#define RBLK 128     // blocks
#define EPB  64      // elements per block (RBLK*EPB = NN)

__global__ void __launch_bounds__(RT) rank_kernel(const float* __restrict__ in) {
    __shared__ unsigned int key[NN];   // 32 KB
    __shared__ float smax[4];
    __shared__ int   spart[EPB];

    const int tid = threadIdx.x;

    // --- phase 1: load raw conf (stash bits in key[]), block max reduce ---
    float m = 0.0f;                                   // conf uniform[0,1) >= 0
    #pragma unroll
    for (int k = 0; k < NN / RT; k++) {
        int j = tid + k * RT;
        float c = in[j * 5 + 4];
        key[j] = __float_as_uint(c);
        m = fmaxf(m, c);
    }
    #pragma unroll
    for (int o = 16; o; o >>= 1) m = fmaxf(m, __shfl_xor_sync(0xFFFFFFFFu, m, o));
    if ((tid & 31) == 0) smax[tid >> 5] = m;
    __syncthreads();
    const float mx = fmaxf(fmaxf(smax[0], smax[1]), fmaxf(smax[2], smax[3]));
    // (deterministic fixed-order reduction -> identical mx in every block)

    // --- phase 2: keys (each thread rewrites only its own slots) ---
    #pragma unroll
    for (int k = 0; k < NN / RT; k++) {
        int j = tid + k * RT;
        float c = __uint_as_float(key[j]);
        key[j] = ~__float_as_uint(__fdiv_rn(c, mx));  // IEEE div, matches jnp
    }
    __syncthreads();

    // --- phase 3: rank by counting (split scan: 2 threads per element) ---
    const int  e  = tid & (EPB - 1);
    const int  i  = blockIdx.x * EPB + e;
    const bool hi = (tid >= EPB);
    const unsigned int Ki = key[i];
    const int lo = hi ? (NN / 2) : 0;
    const int up = lo + NN / 2;

    int r = 0;
    const int b1 = min(up, max(lo, i));        // [lo,b1): j < i -> count <=
    #pragma unroll 8
    for (int j = lo; j < b1; j++) r += (key[j] <= Ki) ? 1 : 0;
    const int a2 = max(lo, min(up, i + 1));    // [a2,up): j > i -> count <
    #pragma unroll 8
    for (int j = a2; j < up; j++) r += (key[j] < Ki) ? 1 : 0;

    if (hi) spart[e] = r;
    __syncthreads();

    // --- scatter: sorted position = rank (unique: strict total order) ---
    if (!hi) {
        int rank = r + spart[e];
        const float* bp = in + i * 5;
        float cx = bp[0], cy = bp[1], w = bp[2], h = bp[3];
        float hw = __fmul_rn(w, 0.5f);
        float hh = __fmul_rn(h, 0.5f);
        g_boxes_s[rank] = make_float4(__fsub_rn(cx, hw), __fsub_rn(cy, hh),
                                      __fadd_rn(cx, hw), __fadd_rn(cy, hh));
        g_conf_s[rank]  = __uint_as_float(~Ki);
    }
}

// ---------------------------------------------------------------------------
// Kernel 2: greedy NMS over sorted valid prefix entirely in smem, then emit
// all 8192 output rows (zeros where suppressed/invalid). Serial loop visits
// only KEPT rows; 1024 threads suppress candidates with exclusive byte
// ownership (r == tid mod T) -> no atomics. Measured 2.08us in R1.
// ---------------------------------------------------------------------------
#define T 1024

__global__ void __launch_bounds__(T, 1) nms_kernel(float* __restrict__ out) {
    extern __shared__ unsigned char dyn[];
    float4*        sbox  = (float4*)dyn;                     // 128 KB
    float*         sarea = (float*)(dyn + NN * 16);          //  32 KB
    unsigned char* skeep = (unsigned char*)(dyn + NN * 20);  //   8 KB
    __shared__ int    scnt[32];
    __shared__ int    s_i;
    __shared__ int    sM;
    __shared__ float4 s_box;
    __shared__ float  s_area;

    const int tid = threadIdx.x;

    // load sorted boxes/conf, set keep=valid, count M (= valid prefix length)
    int cnt = 0;
    for (int p = tid; p < NN; p += T) {
        float4 b = g_boxes_s[p];
        float cf = g_conf_s[p];
        sbox[p]  = b;
        sarea[p] = __fmul_rn(__fsub_rn(b.z, b.x), __fsub_rn(b.w, b.y));
        int v = (cf >= SCORE_TH) ? 1 : 0;
        skeep[p] = (unsigned char)v;
        cnt += v;
    }
    #pragma unroll
    for (int o = 16; o; o >>= 1) cnt += __shfl_xor_sync(0xFFFFFFFFu, cnt, o);
    if ((tid & 31) == 0) scnt[tid >> 5] = cnt;
    if (tid == 0) s_i = -1;
    __syncthreads();
    if (tid == 0) {
        int s = 0;
        #pragma unroll
        for (int w = 0; w < 32; w++) s += scnt[w];
        sM = s;
    }
    __syncthreads();
    const int M = sM;

    while (true) {
        if (tid == 0) {
            int i = s_i + 1;
            while (i < M && !skeep[i]) i++;          // skip suppressed rows
            s_i = i;
            if (i < M) { s_box = sbox[i]; s_area = sarea[i]; }
        }
        __syncthreads();
        const int i = s_i;
        if (i >= M) break;
        const float4 bi = s_box;
        const float  ai = s_area;
        for (int r = tid; r < M; r += T) {
            if (r > i && skeep[r]) {
                float4 bj = sbox[r];
                float ix1 = fmaxf(bi.x, bj.x);
                float iy1 = fmaxf(bi.y, bj.y);
                float ix2 = fminf(bi.z, bj.z);
                float iy2 = fminf(bi.w, bj.w);
                float iw  = fmaxf(__fsub_rn(ix2, ix1), 0.0f);
                float ih  = fmaxf(__fsub_rn(iy2, iy1), 0.0f);
                float inter = __fmul_rn(iw, ih);
                float uni   = __fsub_rn(__fadd_rn(ai, sarea[r]), inter);
                float iou   = __fdiv_rn(inter, fmaxf(uni, 1e-9f));
                if (iou > IOU_TH) skeep[r] = 0;
            }
        }
        __syncthreads();
    }

    // --- emit output: [x1 y1 x2 y2 conf] or zeros ---
    for (int p = tid; p < NN; p += T) {
        float4 b = make_float4(0.f, 0.f, 0.f, 0.f);
        float  cf = 0.f;
        if (skeep[p]) { b = sbox[p]; cf = g_conf_s[p]; }
        float* o = out + p * 5;
        o[0] = b.x; o[1] = b.y; o[2] = b.z; o[3] = b.w; o[4] = cf;
    }
}

// ---------------------------------------------------------------------------
extern "C" void kernel_launch(void* const* d_in, const int* in_sizes, int n_in,
                              void* d_out, int out_size) {
    const float* in = (const float*)d_in[0];
    float* out = (float*)d_out;

    cudaFuncSetAttribute(nms_kernel, cudaFuncAttributeMaxDynamicSharedMemorySize,
                         NN * 21);

    rank_kernel<<<RBLK, RT>>>(in);
    nms_kernel<<<1, T, NN * 21>>>(out);
}